// round 13
// baseline (speedup 1.0000x reference)
#include <cuda_runtime.h>
#include <cuda_bf16.h>
#include <math.h>
#include <stdint.h>

#define TAU 5e-5f
#define MAXFLAG 8192

__device__ int g_hist[32];
__device__ int g_nflag;
__device__ int g_flag[MAXFLAG];
// B image: per (phase,ktile): 2048 u32 hi + 2048 u32 lo (16KB), swizzled bf16 pairs
__device__ uint32_t g_Bimg[2 * 128 * 4096];   // 4 MB

__device__ __forceinline__ uint32_t smem_u32(const void* p) {
    uint32_t a;
    asm("{ .reg .u64 t; cvta.to.shared.u64 t, %1; cvt.u32.u64 %0, t; }" : "=r"(a) : "l"(p));
    return a;
}
__device__ __forceinline__ uint32_t pack_bf16(float x0, float x1) {
    __nv_bfloat16 h0 = __float2bfloat16_rn(x0);
    __nv_bfloat16 h1 = __float2bfloat16_rn(x1);
    return (uint32_t)__bfloat16_as_ushort(h0) | ((uint32_t)__bfloat16_as_ushort(h1) << 16);
}

#define MMA16(c, a, b0_, b1_) \
    asm volatile("mma.sync.aligned.m16n8k16.row.col.f32.bf16.bf16.f32 " \
        "{%0,%1,%2,%3}, {%4,%5,%6,%7}, {%8,%9}, {%0,%1,%2,%3};" \
        : "+f"((c)[0]), "+f"((c)[1]), "+f"((c)[2]), "+f"((c)[3]) \
        : "r"((a)[0]), "r"((a)[1]), "r"((a)[2]), "r"((a)[3]), "r"(b0_), "r"(b1_))

#define LDSM4(r, addr) \
    asm volatile("ldmatrix.sync.aligned.m8n8.x4.shared.b16 {%0,%1,%2,%3}, [%4];" \
        : "=r"((r)[0]), "=r"((r)[1]), "=r"((r)[2]), "=r"((r)[3]) : "r"(addr))

#define CPASYNC16(dst, src) \
    asm volatile("cp.async.cg.shared.global [%0], [%1], 16;" :: "r"(dst), "l"(src))

__global__ void init_kernel() {
    if (threadIdx.x < 32) g_hist[threadIdx.x] = 0;
    if (threadIdx.x == 0) g_nflag = 0;
}

// swizzled u32 offset for element-pair (r = m or n row, kp = k-pair index 0..15)
__device__ __forceinline__ int swz_off(int r, int kp) {
    const int chunk = kp >> 2;                       // 16B chunk (8 bf16 of k)
    const int sw = (((r & 1) << 2) | chunk) ^ ((r >> 1) & 7);
    return (r >> 1) * 32 + sw * 4 + (kp & 3);
}

// ---- prep: W -> bf16 hi/lo, [n][k] transposed, swizzled, packed ----
__global__ void prep_kernel(const float* __restrict__ W0, const float* __restrict__ W1) {
    const int p  = blockIdx.x >> 7;
    const int kt = blockIdx.x & 127;
    const float* W = p ? W1 : W0;
    uint32_t* img = g_Bimg + (size_t)blockIdx.x * 4096;
    const int n = threadIdx.x;
#pragma unroll
    for (int kp = 0; kp < 16; ++kp) {
        const float w0 = W[(size_t)(kt * 32 + kp * 2) * 128 + n];
        const float w1 = W[(size_t)(kt * 32 + kp * 2 + 1) * 128 + n];
        const float h0 = __bfloat162float(__float2bfloat16_rn(w0));
        const float h1 = __bfloat162float(__float2bfloat16_rn(w1));
        const int off = swz_off(n, kp);
        img[off]        = pack_bf16(h0, h1);
        img[2048 + off] = pack_bf16(w0 - h0, w1 - h1);
    }
}

// smem: [0,512) bias | buf0 @512 | buf1 @512+32768   (bytes)
// buffer: Ah @0 (8KB), Al @8192, Bh @16384, Bl @24576
// epilogue overlay: xs = 128 x 132 floats (67584 B total smem)
__global__ __launch_bounds__(256, 2)
void gemm_vq_mma(const float* __restrict__ s0g, const float* __restrict__ s1g,
                 const float* __restrict__ b0g, const float* __restrict__ b1g,
                 const float* __restrict__ Wfg, const float* __restrict__ bfg,
                 const float* __restrict__ cbg, float* __restrict__ out,
                 int N, int Kcb)
{
    extern __shared__ float sm[];
    const uint32_t su = smem_u32(sm);
    const int tid  = threadIdx.x;
    const int lane = tid & 31, wid = tid >> 5;
    const int g = lane >> 2, tig = lane & 3;
    const int wm = wid & 3, wn = wid >> 2;
    const int m0 = blockIdx.x * 128;

    if (tid < 128) sm[tid] = b0g[tid] + b1g[tid];

    const int rowm = ((lane >> 3) & 1) * 8 + (lane & 7);   // ldmatrix row within 16
    const int kblk = lane >> 4;                            // 16B k-block within k16

    float c[2][8][4];
#pragma unroll
    for (int mt = 0; mt < 2; ++mt)
#pragma unroll
        for (int nt = 0; nt < 8; ++nt)
#pragma unroll
            for (int r = 0; r < 4; ++r) c[mt][nt][r] = 0.0f;

    auto ldgA = [&](float4 va[4], int t) {
#pragma unroll
        for (int i = 0; i < 4; ++i) {
            const int u = i * 256 + tid;
            const int row = u >> 3, q = u & 7;
            const float* Ag = (t >> 7) ? s1g : s0g;
            va[i] = *(const float4*)(Ag + (size_t)(m0 + row) * 4096 + (t & 127) * 32 + q * 4);
        }
    };
    auto stsA = [&](uint32_t* buf, const float4 va[4]) {
#pragma unroll
        for (int i = 0; i < 4; ++i) {
            const int u = i * 256 + tid;
            const int row = u >> 3, q = u & 7;
            const float x0 = va[i].x, x1 = va[i].y, x2 = va[i].z, x3 = va[i].w;
            const float h0 = __bfloat162float(__float2bfloat16_rn(x0));
            const float h1 = __bfloat162float(__float2bfloat16_rn(x1));
            const float h2 = __bfloat162float(__float2bfloat16_rn(x2));
            const float h3 = __bfloat162float(__float2bfloat16_rn(x3));
            const int off = swz_off(row, q * 2);   // q*2, q*2+1 share chunk, consecutive u32
            buf[off]            = pack_bf16(h0, h1);
            buf[off + 1]        = pack_bf16(h2, h3);
            buf[2048 + off]     = pack_bf16(x0 - h0, x1 - h1);
            buf[2048 + off + 1] = pack_bf16(x2 - h2, x3 - h3);
        }
    };
    auto cpB = [&](uint32_t dstB, int t) {
        const uint32_t* src = g_Bimg + (size_t)t * 4096;
#pragma unroll
        for (int i = 0; i < 4; ++i) {
            const int u = i * 256 + tid;           // 1024 x 16B = 16KB
            CPASYNC16(dstB + u * 16, src + u * 4);
        }
    };

    float4 va[4];
    ldgA(va, 0);
    cpB(su + 512 + 16384, 0);
    asm volatile("cp.async.commit_group;" ::: "memory");
    stsA((uint32_t*)(sm + 128), va);
    asm volatile("cp.async.wait_group 0;" ::: "memory");
    __syncthreads();

    for (int t = 0; t < 256; ++t) {
        const uint32_t bu = su + 512 + (uint32_t)(t & 1) * 32768u;
        if (t + 1 < 256) {
            ldgA(va, t + 1);
            cpB(su + 512 + (uint32_t)((t + 1) & 1) * 32768u + 16384, t + 1);
            asm volatile("cp.async.commit_group;" ::: "memory");
        }
        // compute tile t
#pragma unroll
        for (int cc = 0; cc < 2; ++cc) {
            uint32_t ah[2][4], al_[2][4];
#pragma unroll
            for (int mt = 0; mt < 2; ++mt) {
                const int m = wm * 32 + mt * 16 + rowm;
                const int ch = cc * 2 + kblk;
                const uint32_t aoff =
                    (uint32_t)((m >> 1) * 128 + (((((m & 1) << 2) | ch) ^ ((m >> 1) & 7)) << 4));
                LDSM4(ah[mt],  bu + aoff);
                LDSM4(al_[mt], bu + 8192 + aoff);
            }
#pragma unroll
            for (int p = 0; p < 4; ++p) {
                const int n = wn * 64 + p * 16 + rowm;
                const int ch = cc * 2 + kblk;
                const uint32_t boff =
                    (uint32_t)((n >> 1) * 128 + (((((n & 1) << 2) | ch) ^ ((n >> 1) & 7)) << 4));
                uint32_t bh[4], bl[4];
                LDSM4(bh, bu + 16384 + boff);
                LDSM4(bl, bu + 24576 + boff);
#pragma unroll
                for (int q = 0; q < 2; ++q) {
                    const int nt = 2 * p + q;
#pragma unroll
                    for (int mt = 0; mt < 2; ++mt) {
                        MMA16(c[mt][nt], ah[mt],  bh[q], bh[q + 2]);   // hi*hi
                        MMA16(c[mt][nt], ah[mt],  bl[q], bl[q + 2]);   // hi*lo
                        MMA16(c[mt][nt], al_[mt], bh[q], bh[q + 2]);   // lo*hi
                    }
                }
            }
        }
        if (t + 1 < 256) stsA((uint32_t*)(sm + 128 + ((t + 1) & 1) * 8192), va);
        asm volatile("cp.async.wait_group 0;" ::: "memory");
        __syncthreads();
    }

    // ---- epilogue: bias to regs, relu -> xs (pad 132: even => float2-aligned) ----
    float breg[16];
#pragma unroll
    for (int nt = 0; nt < 8; ++nt) {
        const int col = wn * 64 + nt * 8 + tig * 2;
        breg[nt * 2]     = sm[col];
        breg[nt * 2 + 1] = sm[col + 1];
    }
    __syncthreads();
    float* xs = sm;
#pragma unroll
    for (int mt = 0; mt < 2; ++mt)
#pragma unroll
        for (int nt = 0; nt < 8; ++nt) {
            const int col = wn * 64 + nt * 8 + tig * 2;
            const int r0 = wm * 32 + mt * 16 + g;
            float2 v0, v1;
            v0.x = fmaxf(c[mt][nt][0] + breg[nt * 2],     0.0f);
            v0.y = fmaxf(c[mt][nt][1] + breg[nt * 2 + 1], 0.0f);
            v1.x = fmaxf(c[mt][nt][2] + breg[nt * 2],     0.0f);
            v1.y = fmaxf(c[mt][nt][3] + breg[nt * 2 + 1], 0.0f);
            *(float2*)(xs + r0 * 132 + col)       = v0;
            *(float2*)(xs + (r0 + 8) * 132 + col) = v1;
        }
    __syncthreads();

    // ---- per-row: fp64 flat, reference distance expansion, margin-checked argmin ----
    if (tid < 128) {
        const float* xr = xs + tid * 132;
        double F0 = 0.0, F1 = 0.0, F2 = 0.0, F3 = 0.0;
#pragma unroll 8
        for (int h = 0; h < 128; ++h) {
            const double xv = (double)xr[h];
            F0 = fma(xv, (double)__ldg(Wfg + h * 4 + 0), F0);
            F1 = fma(xv, (double)__ldg(Wfg + h * 4 + 1), F1);
            F2 = fma(xv, (double)__ldg(Wfg + h * 4 + 2), F2);
            F3 = fma(xv, (double)__ldg(Wfg + h * 4 + 3), F3);
        }
        const float f0 = (float)(F0 + (double)__ldg(bfg + 0));
        const float f1 = (float)(F1 + (double)__ldg(bfg + 1));
        const float f2 = (float)(F2 + (double)__ldg(bfg + 2));
        const float f3 = (float)(F3 + (double)__ldg(bfg + 3));

        const float ff = ((f0 * f0 + f1 * f1) + f2 * f2) + f3 * f3;
        float dmin = 3.4e38f, dsec = 3.4e38f;
        int best = 0;
        for (int k = 0; k < Kcb; ++k) {
            const float c0 = __ldg(cbg + k * 4 + 0), c1 = __ldg(cbg + k * 4 + 1);
            const float c2 = __ldg(cbg + k * 4 + 2), c3 = __ldg(cbg + k * 4 + 3);
            const float cc  = ((c0 * c0 + c1 * c1) + c2 * c2) + c3 * c3;
            const float dot = ((f0 * c0 + f1 * c1) + f2 * c2) + f3 * c3;
            const float tt  = ff + cc;
            const float dk  = tt - 2.0f * dot;
            if (dk < dmin) { dsec = dmin; dmin = dk; best = k; }
            else if (dk < dsec) { dsec = dk; }
        }
        const int gr = m0 + tid;
        if (dsec - dmin < TAU) {
            const int s = atomicAdd(&g_nflag, 1);
            if (s < MAXFLAG) g_flag[s] = gr;
        } else {
            const float c0 = __ldg(cbg + best * 4 + 0), c1 = __ldg(cbg + best * 4 + 1);
            const float c2 = __ldg(cbg + best * 4 + 2), c3 = __ldg(cbg + best * 4 + 3);
            const size_t zbase = (size_t)gr * 4;
            out[zbase + 0] = f0 + (c0 - f0);
            out[zbase + 1] = f1 + (c1 - f1);
            out[zbase + 2] = f2 + (c2 - f2);
            out[zbase + 3] = f3 + (c3 - f3);
            const float d0 = c0 - f0, d1 = c1 - f1, d2 = c2 - f2, d3 = c3 - f3;
            float m = ((d0 * d0 + d1 * d1) + d2 * d2) + d3 * d3;
            m *= 0.25f;
            const size_t zlen = (size_t)N * 4;
            out[zlen + gr] = m + m;
            out[zlen + (size_t)N + 1 + gr] = (float)best;
            atomicAdd(&g_hist[best], 1);
        }
    }
}

// ---- repair: recompute flagged rows with the exact R2 serial fp32 arithmetic ----
__global__ __launch_bounds__(128, 8)
void repair_kernel(const float* __restrict__ s0g, const float* __restrict__ s1g,
                   const float* __restrict__ W0g, const float* __restrict__ b0g,
                   const float* __restrict__ W1g, const float* __restrict__ b1g,
                   const float* __restrict__ Wfg, const float* __restrict__ bfg,
                   const float* __restrict__ cbg, float* __restrict__ out,
                   int N, int Kcb)
{
    const int nf = min(g_nflag, MAXFLAG);
    const int b  = blockIdx.x;
    if (b >= nf) return;
    const int r = g_flag[b];

    __shared__ float xsr[128];
    const int h = threadIdx.x;
    float acc = 0.0f;
    const float* a0 = s0g + (size_t)r * 4096;
#pragma unroll 4
    for (int k = 0; k < 4096; ++k) acc = fmaf(a0[k], __ldg(W0g + (size_t)k * 128 + h), acc);
    const float* a1 = s1g + (size_t)r * 4096;
#pragma unroll 4
    for (int k = 0; k < 4096; ++k) acc = fmaf(a1[k], __ldg(W1g + (size_t)k * 128 + h), acc);
    xsr[h] = fmaxf(acc + (__ldg(b0g + h) + __ldg(b1g + h)), 0.0f);
    __syncthreads();

    if (h == 0) {
        double F0 = 0.0, F1 = 0.0, F2 = 0.0, F3 = 0.0;
        for (int j = 0; j < 128; ++j) {
            const double xv = (double)xsr[j];
            F0 = fma(xv, (double)__ldg(Wfg + j * 4 + 0), F0);
            F1 = fma(xv, (double)__ldg(Wfg + j * 4 + 1), F1);
            F2 = fma(xv, (double)__ldg(Wfg + j * 4 + 2), F2);
            F3 = fma(xv, (double)__ldg(Wfg + j * 4 + 3), F3);
        }
        const float f0 = (float)(F0 + (double)__ldg(bfg + 0));
        const float f1 = (float)(F1 + (double)__ldg(bfg + 1));
        const float f2 = (float)(F2 + (double)__ldg(bfg + 2));
        const float f3 = (float)(F3 + (double)__ldg(bfg + 3));

        const float ff = ((f0 * f0 + f1 * f1) + f2 * f2) + f3 * f3;
        float dmin = 3.4e38f;
        int best = 0;
        for (int k = 0; k < Kcb; ++k) {
            const float c0 = __ldg(cbg + k * 4 + 0), c1 = __ldg(cbg + k * 4 + 1);
            const float c2 = __ldg(cbg + k * 4 + 2), c3 = __ldg(cbg + k * 4 + 3);
            const float cc  = ((c0 * c0 + c1 * c1) + c2 * c2) + c3 * c3;
            const float dot = ((f0 * c0 + f1 * c1) + f2 * c2) + f3 * c3;
            const float tt  = ff + cc;
            const float dk  = tt - 2.0f * dot;
            if (dk < dmin) { dmin = dk; best = k; }
        }
        const float c0 = __ldg(cbg + best * 4 + 0), c1 = __ldg(cbg + best * 4 + 1);
        const float c2 = __ldg(cbg + best * 4 + 2), c3 = __ldg(cbg + best * 4 + 3);
        const size_t zbase = (size_t)r * 4;
        out[zbase + 0] = f0 + (c0 - f0);
        out[zbase + 1] = f1 + (c1 - f1);
        out[zbase + 2] = f2 + (c2 - f2);
        out[zbase + 3] = f3 + (c3 - f3);
        const float d0 = c0 - f0, d1 = c1 - f1, d2 = c2 - f2, d3 = c3 - f3;
        float m = ((d0 * d0 + d1 * d1) + d2 * d2) + d3 * d3;
        m *= 0.25f;
        const size_t zlen = (size_t)N * 4;
        out[zlen + r] = m + m;
        out[zlen + (size_t)N + 1 + r] = (float)best;
        atomicAdd(&g_hist[best], 1);
    }
}

__global__ void finalize_kernel(float* __restrict__ out, int N, int K) {
    if (threadIdx.x == 0) {
        const float invN = 1.0f / (float)N;
        float s = 0.0f;
        for (int k = 0; k < K; ++k) {
            const float p = (float)g_hist[k] * invN;
            s += p * logf(p + 1e-10f);
        }
        out[(size_t)N * 4 + N] = expf(-s);  // perplexity
    }
}

extern "C" void kernel_launch(void* const* d_in, const int* in_sizes, int n_in,
                              void* d_out, int out_size) {
    const float* s0 = (const float*)d_in[0];
    const float* s1 = (const float*)d_in[1];
    const float* W0 = (const float*)d_in[2];
    const float* b0 = (const float*)d_in[3];
    const float* W1 = (const float*)d_in[4];
    const float* b1 = (const float*)d_in[5];
    const float* Wf = (const float*)d_in[6];
    const float* bf = (const float*)d_in[7];
    const float* cb = (const float*)d_in[8];
    float* out = (float*)d_out;

    const int H = in_sizes[3];         // 128
    const int E = in_sizes[7];         // 4
    const int K = in_sizes[8] / E;     // 30
    const int D = in_sizes[2] / H;     // 4096
    const int N = in_sizes[0] / D;     // 32768

    const int smem_bytes = 128 * 132 * (int)sizeof(float);  // 67584 >= 512+2*32768
    cudaFuncSetAttribute(gemm_vq_mma,
                         cudaFuncAttributeMaxDynamicSharedMemorySize, smem_bytes);

    init_kernel<<<1, 32>>>();
    prep_kernel<<<256, 128>>>(W0, W1);
    gemm_vq_mma<<<N / 128, 256, smem_bytes>>>(s0, s1, b0, b1, Wf, bf, cb, out, N, K);
    repair_kernel<<<MAXFLAG, 128>>>(s0, s1, W0, b0, W1, b1, Wf, bf, cb, out, N, K);
    finalize_kernel<<<1, 32>>>(out, N, K);
}

// round 16
// speedup vs baseline: 1.0142x; 1.0142x over previous
#include <cuda_runtime.h>
#include <cuda_bf16.h>
#include <math.h>
#include <stdint.h>

#define TAU 5e-5f
#define MAXFLAG 8192

__device__ int g_hist[32];
__device__ int g_nflag;
__device__ int g_flag[MAXFLAG];
// B image: per (phase,ktile): 2048 u32 hi + 2048 u32 lo (16KB), swizzled bf16 pairs
__device__ uint32_t g_Bimg[2 * 128 * 4096];   // 4 MB

__device__ __forceinline__ uint32_t smem_u32(const void* p) {
    uint32_t a;
    asm("{ .reg .u64 t; cvta.to.shared.u64 t, %1; cvt.u32.u64 %0, t; }" : "=r"(a) : "l"(p));
    return a;
}
__device__ __forceinline__ uint32_t pack_bf16(float x0, float x1) {
    __nv_bfloat16 h0 = __float2bfloat16_rn(x0);
    __nv_bfloat16 h1 = __float2bfloat16_rn(x1);
    return (uint32_t)__bfloat16_as_ushort(h0) | ((uint32_t)__bfloat16_as_ushort(h1) << 16);
}

#define MMA16(c, a, b0_, b1_) \
    asm volatile("mma.sync.aligned.m16n8k16.row.col.f32.bf16.bf16.f32 " \
        "{%0,%1,%2,%3}, {%4,%5,%6,%7}, {%8,%9}, {%0,%1,%2,%3};" \
        : "+f"((c)[0]), "+f"((c)[1]), "+f"((c)[2]), "+f"((c)[3]) \
        : "r"((a)[0]), "r"((a)[1]), "r"((a)[2]), "r"((a)[3]), "r"(b0_), "r"(b1_))

#define LDSM4(r, addr) \
    asm volatile("ldmatrix.sync.aligned.m8n8.x4.shared.b16 {%0,%1,%2,%3}, [%4];" \
        : "=r"((r)[0]), "=r"((r)[1]), "=r"((r)[2]), "=r"((r)[3]) : "r"(addr))

#define CPASYNC16(dst, src) \
    asm volatile("cp.async.cg.shared.global [%0], [%1], 16;" :: "r"(dst), "l"(src))

__global__ void init_kernel() {
    if (threadIdx.x < 32) g_hist[threadIdx.x] = 0;
    if (threadIdx.x == 0) g_nflag = 0;
}

// swizzled u32 offset for element-pair (r = m or n row, kp = k-pair index 0..15)
__device__ __forceinline__ int swz_off(int r, int kp) {
    const int chunk = kp >> 2;                       // 16B chunk (8 bf16 of k)
    const int sw = (((r & 1) << 2) | chunk) ^ ((r >> 1) & 7);
    return (r >> 1) * 32 + sw * 4 + (kp & 3);
}

// ---- prep: W -> bf16 hi/lo, [n][k] transposed, swizzled, packed ----
__global__ void prep_kernel(const float* __restrict__ W0, const float* __restrict__ W1) {
    const int p  = blockIdx.x >> 7;
    const int kt = blockIdx.x & 127;
    const float* W = p ? W1 : W0;
    uint32_t* img = g_Bimg + (size_t)blockIdx.x * 4096;
    const int n = threadIdx.x;
#pragma unroll
    for (int kp = 0; kp < 16; ++kp) {
        const float w0 = W[(size_t)(kt * 32 + kp * 2) * 128 + n];
        const float w1 = W[(size_t)(kt * 32 + kp * 2 + 1) * 128 + n];
        const float h0 = __bfloat162float(__float2bfloat16_rn(w0));
        const float h1 = __bfloat162float(__float2bfloat16_rn(w1));
        const int off = swz_off(n, kp);
        img[off]        = pack_bf16(h0, h1);
        img[2048 + off] = pack_bf16(w0 - h0, w1 - h1);
    }
}

// smem: [0,512) bias | buf0 @512 | buf1 @512+32768   (bytes)
// buffer: Ah @0 (8KB), Al @8192, Bh @16384, Bl @24576
// epilogue overlay: xs = 128 x 132 floats (67584 B total smem)
__global__ __launch_bounds__(256, 2)
void gemm_vq_mma(const float* __restrict__ s0g, const float* __restrict__ s1g,
                 const float* __restrict__ b0g, const float* __restrict__ b1g,
                 const float* __restrict__ Wfg, const float* __restrict__ bfg,
                 const float* __restrict__ cbg, float* __restrict__ out,
                 int N, int Kcb)
{
    extern __shared__ float sm[];
    const uint32_t su = smem_u32(sm);
    const int tid  = threadIdx.x;
    const int lane = tid & 31, wid = tid >> 5;
    const int g = lane >> 2, tig = lane & 3;
    const int wm = wid & 3, wn = wid >> 2;
    const int m0 = blockIdx.x * 128;

    if (tid < 128) sm[tid] = b0g[tid] + b1g[tid];

    const int rowm = ((lane >> 3) & 1) * 8 + (lane & 7);   // ldmatrix row within 16
    const int kblk = lane >> 4;                            // 16B k-block within k16

    float c[2][8][4];
#pragma unroll
    for (int mt = 0; mt < 2; ++mt)
#pragma unroll
        for (int nt = 0; nt < 8; ++nt)
#pragma unroll
            for (int r = 0; r < 4; ++r) c[mt][nt][r] = 0.0f;

    auto ldgA = [&](float4 va[4], int t) {
#pragma unroll
        for (int i = 0; i < 4; ++i) {
            const int u = i * 256 + tid;
            const int row = u >> 3, q = u & 7;
            const float* Ag = (t >> 7) ? s1g : s0g;
            va[i] = *(const float4*)(Ag + (size_t)(m0 + row) * 4096 + (t & 127) * 32 + q * 4);
        }
    };
    auto stsA = [&](uint32_t* buf, const float4 va[4]) {
#pragma unroll
        for (int i = 0; i < 4; ++i) {
            const int u = i * 256 + tid;
            const int row = u >> 3, q = u & 7;
            const float x0 = va[i].x, x1 = va[i].y, x2 = va[i].z, x3 = va[i].w;
            const float h0 = __bfloat162float(__float2bfloat16_rn(x0));
            const float h1 = __bfloat162float(__float2bfloat16_rn(x1));
            const float h2 = __bfloat162float(__float2bfloat16_rn(x2));
            const float h3 = __bfloat162float(__float2bfloat16_rn(x3));
            const int off = swz_off(row, q * 2);   // q*2, q*2+1 share chunk, consecutive u32
            buf[off]            = pack_bf16(h0, h1);
            buf[off + 1]        = pack_bf16(h2, h3);
            buf[2048 + off]     = pack_bf16(x0 - h0, x1 - h1);
            buf[2048 + off + 1] = pack_bf16(x2 - h2, x3 - h3);
        }
    };
    auto cpB = [&](uint32_t dstB, int t) {
        const uint32_t* src = g_Bimg + (size_t)t * 4096;
#pragma unroll
        for (int i = 0; i < 4; ++i) {
            const int u = i * 256 + tid;           // 1024 x 16B = 16KB
            CPASYNC16(dstB + u * 16, src + u * 4);
        }
    };

    float4 va[4];
    ldgA(va, 0);
    cpB(su + 512 + 16384, 0);
    asm volatile("cp.async.commit_group;" ::: "memory");
    stsA((uint32_t*)(sm + 128), va);
    asm volatile("cp.async.wait_group 0;" ::: "memory");
    __syncthreads();

    for (int t = 0; t < 256; ++t) {
        const uint32_t bu = su + 512 + (uint32_t)(t & 1) * 32768u;
        if (t + 1 < 256) {
            ldgA(va, t + 1);
            cpB(su + 512 + (uint32_t)((t + 1) & 1) * 32768u + 16384, t + 1);
            asm volatile("cp.async.commit_group;" ::: "memory");
        }
        // compute tile t
#pragma unroll
        for (int cc = 0; cc < 2; ++cc) {
            uint32_t ah[2][4], al_[2][4];
#pragma unroll
            for (int mt = 0; mt < 2; ++mt) {
                const int m = wm * 32 + mt * 16 + rowm;
                const int ch = cc * 2 + kblk;
                const uint32_t aoff =
                    (uint32_t)((m >> 1) * 128 + (((((m & 1) << 2) | ch) ^ ((m >> 1) & 7)) << 4));
                LDSM4(ah[mt],  bu + aoff);
                LDSM4(al_[mt], bu + 8192 + aoff);
            }
#pragma unroll
            for (int p = 0; p < 4; ++p) {
                const int n = wn * 64 + p * 16 + rowm;
                const int ch = cc * 2 + kblk;
                const uint32_t boff =
                    (uint32_t)((n >> 1) * 128 + (((((n & 1) << 2) | ch) ^ ((n >> 1) & 7)) << 4));
                uint32_t bh[4], bl[4];
                LDSM4(bh, bu + 16384 + boff);
                LDSM4(bl, bu + 24576 + boff);
#pragma unroll
                for (int q = 0; q < 2; ++q) {
                    const int nt = 2 * p + q;
#pragma unroll
                    for (int mt = 0; mt < 2; ++mt) {
                        MMA16(c[mt][nt], ah[mt],  bh[q], bh[q + 2]);   // hi*hi
                        MMA16(c[mt][nt], ah[mt],  bl[q], bl[q + 2]);   // hi*lo
                        MMA16(c[mt][nt], al_[mt], bh[q], bh[q + 2]);   // lo*hi
                    }
                }
            }
        }
        if (t + 1 < 256) stsA((uint32_t*)(sm + 128 + ((t + 1) & 1) * 8192), va);
        asm volatile("cp.async.wait_group 0;" ::: "memory");
        __syncthreads();
    }

    // ---- epilogue: bias to regs, relu -> xs (pad 132: even => float2-aligned) ----
    float breg[16];
#pragma unroll
    for (int nt = 0; nt < 8; ++nt) {
        const int col = wn * 64 + nt * 8 + tig * 2;
        breg[nt * 2]     = sm[col];
        breg[nt * 2 + 1] = sm[col + 1];
    }
    __syncthreads();
    float* xs = sm;
#pragma unroll
    for (int mt = 0; mt < 2; ++mt)
#pragma unroll
        for (int nt = 0; nt < 8; ++nt) {
            const int col = wn * 64 + nt * 8 + tig * 2;
            const int r0 = wm * 32 + mt * 16 + g;
            float2 v0, v1;
            v0.x = fmaxf(c[mt][nt][0] + breg[nt * 2],     0.0f);
            v0.y = fmaxf(c[mt][nt][1] + breg[nt * 2 + 1], 0.0f);
            v1.x = fmaxf(c[mt][nt][2] + breg[nt * 2],     0.0f);
            v1.y = fmaxf(c[mt][nt][3] + breg[nt * 2 + 1], 0.0f);
            *(float2*)(xs + r0 * 132 + col)       = v0;
            *(float2*)(xs + (r0 + 8) * 132 + col) = v1;
        }
    __syncthreads();

    // ---- per-row: fp64 flat, reference distance expansion, margin-checked argmin ----
    if (tid < 128) {
        const float* xr = xs + tid * 132;
        double F0 = 0.0, F1 = 0.0, F2 = 0.0, F3 = 0.0;
#pragma unroll 8
        for (int h = 0; h < 128; ++h) {
            const double xv = (double)xr[h];
            F0 = fma(xv, (double)__ldg(Wfg + h * 4 + 0), F0);
            F1 = fma(xv, (double)__ldg(Wfg + h * 4 + 1), F1);
            F2 = fma(xv, (double)__ldg(Wfg + h * 4 + 2), F2);
            F3 = fma(xv, (double)__ldg(Wfg + h * 4 + 3), F3);
        }
        const float f0 = (float)(F0 + (double)__ldg(bfg + 0));
        const float f1 = (float)(F1 + (double)__ldg(bfg + 1));
        const float f2 = (float)(F2 + (double)__ldg(bfg + 2));
        const float f3 = (float)(F3 + (double)__ldg(bfg + 3));

        const float ff = ((f0 * f0 + f1 * f1) + f2 * f2) + f3 * f3;
        float dmin = 3.4e38f, dsec = 3.4e38f;
        int best = 0;
        for (int k = 0; k < Kcb; ++k) {
            const float c0 = __ldg(cbg + k * 4 + 0), c1 = __ldg(cbg + k * 4 + 1);
            const float c2 = __ldg(cbg + k * 4 + 2), c3 = __ldg(cbg + k * 4 + 3);
            const float cc  = ((c0 * c0 + c1 * c1) + c2 * c2) + c3 * c3;
            const float dot = ((f0 * c0 + f1 * c1) + f2 * c2) + f3 * c3;
            const float tt  = ff + cc;
            const float dk  = tt - 2.0f * dot;
            if (dk < dmin) { dsec = dmin; dmin = dk; best = k; }
            else if (dk < dsec) { dsec = dk; }
        }
        const int gr = m0 + tid;
        if (dsec - dmin < TAU) {
            const int s = atomicAdd(&g_nflag, 1);
            if (s < MAXFLAG) g_flag[s] = gr;
        } else {
            const float c0 = __ldg(cbg + best * 4 + 0), c1 = __ldg(cbg + best * 4 + 1);
            const float c2 = __ldg(cbg + best * 4 + 2), c3 = __ldg(cbg + best * 4 + 3);
            const size_t zbase = (size_t)gr * 4;
            out[zbase + 0] = f0 + (c0 - f0);
            out[zbase + 1] = f1 + (c1 - f1);
            out[zbase + 2] = f2 + (c2 - f2);
            out[zbase + 3] = f3 + (c3 - f3);
            const float d0 = c0 - f0, d1 = c1 - f1, d2 = c2 - f2, d3 = c3 - f3;
            float m = ((d0 * d0 + d1 * d1) + d2 * d2) + d3 * d3;
            m *= 0.25f;
            const size_t zlen = (size_t)N * 4;
            out[zlen + gr] = m + m;
            out[zlen + (size_t)N + 1 + gr] = (float)best;
            atomicAdd(&g_hist[best], 1);
        }
    }
}

// ---- repair: recompute flagged rows with the exact R2 serial fp32 arithmetic ----
__global__ __launch_bounds__(128, 8)
void repair_kernel(const float* __restrict__ s0g, const float* __restrict__ s1g,
                   const float* __restrict__ W0g, const float* __restrict__ b0g,
                   const float* __restrict__ W1g, const float* __restrict__ b1g,
                   const float* __restrict__ Wfg, const float* __restrict__ bfg,
                   const float* __restrict__ cbg, float* __restrict__ out,
                   int N, int Kcb)
{
    const int nf = min(g_nflag, MAXFLAG);
    const int b  = blockIdx.x;
    if (b >= nf) return;
    const int r = g_flag[b];

    __shared__ float xsr[128];
    const int h = threadIdx.x;
    float acc = 0.0f;
    const float* a0 = s0g + (size_t)r * 4096;
#pragma unroll 4
    for (int k = 0; k < 4096; ++k) acc = fmaf(a0[k], __ldg(W0g + (size_t)k * 128 + h), acc);
    const float* a1 = s1g + (size_t)r * 4096;
#pragma unroll 4
    for (int k = 0; k < 4096; ++k) acc = fmaf(a1[k], __ldg(W1g + (size_t)k * 128 + h), acc);
    xsr[h] = fmaxf(acc + (__ldg(b0g + h) + __ldg(b1g + h)), 0.0f);
    __syncthreads();

    if (h == 0) {
        double F0 = 0.0, F1 = 0.0, F2 = 0.0, F3 = 0.0;
        for (int j = 0; j < 128; ++j) {
            const double xv = (double)xsr[j];
            F0 = fma(xv, (double)__ldg(Wfg + j * 4 + 0), F0);
            F1 = fma(xv, (double)__ldg(Wfg + j * 4 + 1), F1);
            F2 = fma(xv, (double)__ldg(Wfg + j * 4 + 2), F2);
            F3 = fma(xv, (double)__ldg(Wfg + j * 4 + 3), F3);
        }
        const float f0 = (float)(F0 + (double)__ldg(bfg + 0));
        const float f1 = (float)(F1 + (double)__ldg(bfg + 1));
        const float f2 = (float)(F2 + (double)__ldg(bfg + 2));
        const float f3 = (float)(F3 + (double)__ldg(bfg + 3));

        const float ff = ((f0 * f0 + f1 * f1) + f2 * f2) + f3 * f3;
        float dmin = 3.4e38f;
        int best = 0;
        for (int k = 0; k < Kcb; ++k) {
            const float c0 = __ldg(cbg + k * 4 + 0), c1 = __ldg(cbg + k * 4 + 1);
            const float c2 = __ldg(cbg + k * 4 + 2), c3 = __ldg(cbg + k * 4 + 3);
            const float cc  = ((c0 * c0 + c1 * c1) + c2 * c2) + c3 * c3;
            const float dot = ((f0 * c0 + f1 * c1) + f2 * c2) + f3 * c3;
            const float tt  = ff + cc;
            const float dk  = tt - 2.0f * dot;
            if (dk < dmin) { dmin = dk; best = k; }
        }
        const float c0 = __ldg(cbg + best * 4 + 0), c1 = __ldg(cbg + best * 4 + 1);
        const float c2 = __ldg(cbg + best * 4 + 2), c3 = __ldg(cbg + best * 4 + 3);
        const size_t zbase = (size_t)r * 4;
        out[zbase + 0] = f0 + (c0 - f0);
        out[zbase + 1] = f1 + (c1 - f1);
        out[zbase + 2] = f2 + (c2 - f2);
        out[zbase + 3] = f3 + (c3 - f3);
        const float d0 = c0 - f0, d1 = c1 - f1, d2 = c2 - f2, d3 = c3 - f3;
        float m = ((d0 * d0 + d1 * d1) + d2 * d2) + d3 * d3;
        m *= 0.25f;
        const size_t zlen = (size_t)N * 4;
        out[zlen + r] = m + m;
        out[zlen + (size_t)N + 1 + r] = (float)best;
        atomicAdd(&g_hist[best], 1);
    }
}

__global__ void finalize_kernel(float* __restrict__ out, int N, int K) {
    if (threadIdx.x == 0) {
        const float invN = 1.0f / (float)N;
        float s = 0.0f;
        for (int k = 0; k < K; ++k) {
            const float p = (float)g_hist[k] * invN;
            s += p * logf(p + 1e-10f);
        }
        out[(size_t)N * 4 + N] = expf(-s);  // perplexity
    }
}

extern "C" void kernel_launch(void* const* d_in, const int* in_sizes, int n_in,
                              void* d_out, int out_size) {
    const float* s0 = (const float*)d_in[0];
    const float* s1 = (const float*)d_in[1];
    const float* W0 = (const float*)d_in[2];
    const float* b0 = (const float*)d_in[3];
    const float* W1 = (const float*)d_in[4];
    const float* b1 = (const float*)d_in[5];
    const float* Wf = (const float*)d_in[6];
    const float* bf = (const float*)d_in[7];
    const float* cb = (const float*)d_in[8];
    float* out = (float*)d_out;

    const int H = in_sizes[3];         // 128
    const int E = in_sizes[7];         // 4
    const int K = in_sizes[8] / E;     // 30
    const int D = in_sizes[2] / H;     // 4096
    const int N = in_sizes[0] / D;     // 32768

    const int smem_bytes = 128 * 132 * (int)sizeof(float);  // 67584 >= 512+2*32768
    cudaFuncSetAttribute(gemm_vq_mma,
                         cudaFuncAttributeMaxDynamicSharedMemorySize, smem_bytes);

    init_kernel<<<1, 32>>>();
    prep_kernel<<<256, 128>>>(W0, W1);
    gemm_vq_mma<<<N / 128, 256, smem_bytes>>>(s0, s1, b0, b1, Wf, bf, cb, out, N, K);
    repair_kernel<<<MAXFLAG, 128>>>(s0, s1, W0, b0, W1, b1, Wf, bf, cb, out, N, K);
    finalize_kernel<<<1, 32>>>(out, N, K);
}